// round 5
// baseline (speedup 1.0000x reference)
#include <cuda_runtime.h>
#include <math.h>

#define BB 32
#define HWT 12544              // 112*112
#define CC 256
#define HID 32
#define F4_PER_ROW 64          // 256 / 4

#define NPOOL 392              // pooler CTAs (32 rows per batch each)
#define NSCAL 784              // scaler CTAs (16 rows per batch each)
#define GRID_CTAS (NPOOL + NSCAL)   // 1176 <= 8/SM * 147 SMs (all co-resident)
#define DW 6                   // L2 window depth in batches (~77MB)

__device__ float g_psum[BB][NPOOL][CC];
__device__ float g_pmax[BB][NPOOL][CC];
__device__ float g_scale[BB][CC];
__device__ int   g_pcnt[BB];
__device__ int   g_flag[BB];
__device__ int   g_scnt[BB];
__device__ int   g_srel[BB];

__global__ void init_kernel() {
    int t = threadIdx.x;
    if (t < BB) { g_pcnt[t] = 0; g_flag[t] = 0; g_scnt[t] = 0; g_srel[t] = 0; }
}

__global__ void __launch_bounds__(256, 8) fused_pc_kernel(
    const float* __restrict__ x,
    const float* __restrict__ w1, const float* __restrict__ b1,
    const float* __restrict__ w2, const float* __restrict__ b2,
    float* __restrict__ out)
{
    const int cta = blockIdx.x;
    const int tid = threadIdx.x;
    const int c4  = tid & 63;     // float4 channel group
    const int rg  = tid >> 6;     // 0..3

    if (cta < NPOOL) {
        // ================= POOLER =================
        const int p = cta;
        __shared__ float4 s_sum[4][64];
        __shared__ float4 s_mx4[4][64];
        __shared__ int    s_last;

        for (int b = 0; b < BB; ++b) {
            // L2-window gate: WAIT (bounded) until scalers finished batch b-DW.
            // Pure performance hint — x is immutable, so proceeding is always safe.
            if (b >= DW && tid == 0) {
                int tries = 0;
                while (((volatile int*)g_srel)[b - DW] == 0 && tries < 60000) {
                    __nanosleep(128); ++tries;
                }
            }
            __syncthreads();

            // pool 32 rows: thread handles 8 rows of its float4 column
            const size_t row0 = (size_t)b * HWT + (size_t)p * 32 + (size_t)rg * 8;
            const float4* __restrict__ xp =
                reinterpret_cast<const float4*>(x) + row0 * F4_PER_ROW + c4;
            float4 s = make_float4(0.f, 0.f, 0.f, 0.f);
            float4 m = make_float4(-INFINITY, -INFINITY, -INFINITY, -INFINITY);
            #pragma unroll
            for (int r = 0; r < 8; ++r) {
                float4 v = __ldcg(xp + (size_t)r * F4_PER_ROW);
                s.x += v.x; s.y += v.y; s.z += v.z; s.w += v.w;
                m.x = fmaxf(m.x, v.x); m.y = fmaxf(m.y, v.y);
                m.z = fmaxf(m.z, v.z); m.w = fmaxf(m.w, v.w);
            }
            s_sum[rg][c4] = s;
            s_mx4[rg][c4] = m;
            __syncthreads();

            if (rg == 0) {
                float4 a0 = s_sum[0][c4], a1 = s_sum[1][c4], a2 = s_sum[2][c4], a3 = s_sum[3][c4];
                float4 m0 = s_mx4[0][c4], m1 = s_mx4[1][c4], m2 = s_mx4[2][c4], m3 = s_mx4[3][c4];
                float4 ss = make_float4(a0.x + a1.x + a2.x + a3.x,
                                        a0.y + a1.y + a2.y + a3.y,
                                        a0.z + a1.z + a2.z + a3.z,
                                        a0.w + a1.w + a2.w + a3.w);
                float4 mm = make_float4(fmaxf(fmaxf(m0.x, m1.x), fmaxf(m2.x, m3.x)),
                                        fmaxf(fmaxf(m0.y, m1.y), fmaxf(m2.y, m3.y)),
                                        fmaxf(fmaxf(m0.z, m1.z), fmaxf(m2.z, m3.z)),
                                        fmaxf(fmaxf(m0.w, m1.w), fmaxf(m2.w, m3.w)));
                reinterpret_cast<float4*>(&g_psum[b][p][0])[c4] = ss;
                reinterpret_cast<float4*>(&g_pmax[b][p][0])[c4] = mm;
            }
            __threadfence();           // release partials
            __syncthreads();

            if (tid == 0) {
                int old = atomicAdd(&g_pcnt[b], 1);
                s_last = (old == NPOOL - 1);
                if (s_last) __threadfence();   // acquire all partials
            }
            __syncthreads();

            if (s_last) {
                // ---- fan-in tail: reduce NPOOL partials + MLP + sigmoid ----
                __shared__ float s_avg[CC];
                __shared__ float s_max[CC];
                __shared__ float s_h[2 * HID];

                float sum = 0.f, mx = -INFINITY;
                #pragma unroll 8
                for (int q = 0; q < NPOOL; ++q) {
                    sum += __ldcg(&g_psum[b][q][tid]);
                    mx = fmaxf(mx, __ldcg(&g_pmax[b][q][tid]));
                }
                s_avg[tid] = sum * (1.0f / (float)HWT);
                s_max[tid] = mx;
                __syncthreads();

                {   // hidden layer: 64 outputs (avg 0..31, max 32..63), 4 thr/out
                    int oi = tid >> 2;
                    int part = tid & 3;
                    int j = oi & (HID - 1);
                    const float* pool = (oi < HID) ? s_avg : s_max;
                    float acc = 0.f;
                    #pragma unroll 16
                    for (int i = part * 64; i < part * 64 + 64; ++i)
                        acc += pool[i] * w1[i * HID + j];
                    acc += __shfl_down_sync(0xffffffffu, acc, 1);
                    acc += __shfl_down_sync(0xffffffffu, acc, 2);
                    if (part == 0) s_h[oi] = fmaxf(acc + b1[j], 0.f);
                }
                __syncthreads();

                {   // output layer: 2*b2 + (hA+hM) @ w2, sigmoid
                    float acc = 2.0f * b2[tid];
                    #pragma unroll
                    for (int j = 0; j < HID; ++j)
                        acc += (s_h[j] + s_h[HID + j]) * w2[j * CC + tid];
                    g_scale[b][tid] = 1.0f / (1.0f + expf(-acc));
                }
                __threadfence();       // release g_scale
                __syncthreads();
                if (tid == 0) atomicExch(&g_flag[b], 1);
            }
        }
    } else {
        // ================= SCALER =================
        const int sidx = cta - NPOOL;

        for (int b = 0; b < BB; ++b) {
            if (tid == 0) {
                while (((volatile int*)g_flag)[b] == 0) __nanosleep(256);
                __threadfence();       // acquire g_scale (and x window)
            }
            __syncthreads();

            const float4 sc = __ldcg(reinterpret_cast<const float4*>(&g_scale[b][0]) + c4);

            // 16 rows per scaler CTA: thread handles 4 rows of its column
            const size_t row0 = (size_t)b * HWT + (size_t)sidx * 16 + (size_t)rg * 4;
            const float4* __restrict__ xi =
                reinterpret_cast<const float4*>(x) + row0 * F4_PER_ROW + c4;
            float4* __restrict__ xo =
                reinterpret_cast<float4*>(out) + row0 * F4_PER_ROW + c4;
            #pragma unroll
            for (int r = 0; r < 4; ++r) {
                float4 v = __ldcs(xi + (size_t)r * F4_PER_ROW);   // L2-hot, evict-first
                v.x *= sc.x; v.y *= sc.y; v.z *= sc.z; v.w *= sc.w;
                __stcs(xo + (size_t)r * F4_PER_ROW, v);
            }
            __syncthreads();
            if (tid == 0) {
                int old = atomicAdd(&g_scnt[b], 1);
                if (old == NSCAL - 1) ((volatile int*)g_srel)[b] = 1;  // window release (hint)
            }
        }
    }
}

extern "C" void kernel_launch(void* const* d_in, const int* in_sizes, int n_in,
                              void* d_out, int out_size) {
    const float* x  = (const float*)d_in[0];
    const float* w1 = (const float*)d_in[1];
    const float* b1 = (const float*)d_in[2];
    const float* w2 = (const float*)d_in[3];
    const float* b2 = (const float*)d_in[4];
    float* out = (float*)d_out;

    init_kernel<<<1, 32>>>();
    fused_pc_kernel<<<GRID_CTAS, 256>>>(x, w1, b1, w2, b2, out);
}

// round 6
// speedup vs baseline: 6.7338x; 6.7338x over previous
#include <cuda_runtime.h>
#include <math.h>

#define BB 32
#define HWT 12544              // 112*112
#define CC 256
#define HID 32
#define F4_PER_ROW 64          // 256 / 4

#define GROUP 4                // batches per group (51.4MB)
#define NGRP 8                 // 8 * 4 = 32
#define KCTA 128               // pool CTAs per batch -> grid 512
#define ROWS_CTA 98            // HWT / KCTA

#define BLOCKS_S 196           // scale CTAs per batch -> grid 784
#define F4_PER_B ((size_t)HWT * F4_PER_ROW)   // 802816
#define F4_PER_SCTA (F4_PER_B / BLOCKS_S)     // 4096

__device__ float g_psum[BB][KCTA][CC];
__device__ float g_pmax[BB][KCTA][CC];
__device__ float g_scale[BB][CC];
__device__ int   g_cnt[BB];    // zero at load; self-resetting

// ---- host-side streams/events (no device memory) ----
static cudaStream_t s1, s2;
static cudaEvent_t evRoot, evP[NGRP], evS[NGRP];
static struct StreamInit {
    StreamInit() {
        cudaStreamCreateWithFlags(&s1, cudaStreamNonBlocking);
        cudaStreamCreateWithFlags(&s2, cudaStreamNonBlocking);
        cudaEventCreateWithFlags(&evRoot, cudaEventDisableTiming);
        for (int i = 0; i < NGRP; ++i) {
            cudaEventCreateWithFlags(&evP[i], cudaEventDisableTiming);
            cudaEventCreateWithFlags(&evS[i], cudaEventDisableTiming);
        }
    }
} s_init;

// Kernel A: pool GROUP batches + fan-in MLP tail. grid (KCTA, GROUP), 256 thr.
__global__ void __launch_bounds__(256) pool_mlp_kernel(
    const float* __restrict__ x,
    const float* __restrict__ w1, const float* __restrict__ b1,
    const float* __restrict__ w2, const float* __restrict__ b2,
    int b0)
{
    const int b   = b0 + blockIdx.y;
    const int k   = blockIdx.x;
    const int tid = threadIdx.x;
    const int c4  = tid & 63;
    const int rg  = tid >> 6;

    __shared__ float4 s_sum[4][64];
    __shared__ float4 s_mx4[4][64];
    __shared__ int    s_last;

    const size_t rowb = (size_t)b * HWT + (size_t)k * ROWS_CTA;
    const float4* __restrict__ xp = reinterpret_cast<const float4*>(x) + rowb * F4_PER_ROW + c4;

    float4 s = make_float4(0.f, 0.f, 0.f, 0.f);
    float4 m = make_float4(-INFINITY, -INFINITY, -INFINITY, -INFINITY);
    // rows rg, rg+4, ..., < 98  (24 or 25 rows per thread)
    #pragma unroll 6
    for (int r = rg; r < ROWS_CTA; r += 4) {
        float4 v = __ldcg(xp + (size_t)r * F4_PER_ROW);
        s.x += v.x; s.y += v.y; s.z += v.z; s.w += v.w;
        m.x = fmaxf(m.x, v.x); m.y = fmaxf(m.y, v.y);
        m.z = fmaxf(m.z, v.z); m.w = fmaxf(m.w, v.w);
    }
    s_sum[rg][c4] = s;
    s_mx4[rg][c4] = m;
    __syncthreads();

    if (rg == 0) {
        float4 a0 = s_sum[0][c4], a1 = s_sum[1][c4], a2 = s_sum[2][c4], a3 = s_sum[3][c4];
        float4 m0 = s_mx4[0][c4], m1 = s_mx4[1][c4], m2 = s_mx4[2][c4], m3 = s_mx4[3][c4];
        float4 ss = make_float4(a0.x + a1.x + a2.x + a3.x,
                                a0.y + a1.y + a2.y + a3.y,
                                a0.z + a1.z + a2.z + a3.z,
                                a0.w + a1.w + a2.w + a3.w);
        float4 mm = make_float4(fmaxf(fmaxf(m0.x, m1.x), fmaxf(m2.x, m3.x)),
                                fmaxf(fmaxf(m0.y, m1.y), fmaxf(m2.y, m3.y)),
                                fmaxf(fmaxf(m0.z, m1.z), fmaxf(m2.z, m3.z)),
                                fmaxf(fmaxf(m0.w, m1.w), fmaxf(m2.w, m3.w)));
        reinterpret_cast<float4*>(&g_psum[b][k][0])[c4] = ss;
        reinterpret_cast<float4*>(&g_pmax[b][k][0])[c4] = mm;
    }
    __threadfence();           // release partials
    __syncthreads();

    if (tid == 0) {
        int old = atomicAdd(&g_cnt[b], 1);
        s_last = (old == KCTA - 1);
        if (s_last) {
            g_cnt[b] = 0;      // self-reset for graph replays
            __threadfence();   // acquire partials
        }
    }
    __syncthreads();
    if (!s_last) return;

    // ---- fan-in tail: reduce KCTA partials + dual-branch MLP + sigmoid ----
    __shared__ float s_avg[CC];
    __shared__ float s_max[CC];
    __shared__ float s_h[2 * HID];

    float sum = 0.f, mx = -INFINITY;
    #pragma unroll 16
    for (int q = 0; q < KCTA; ++q) {
        sum += __ldcg(&g_psum[b][q][tid]);
        mx = fmaxf(mx, __ldcg(&g_pmax[b][q][tid]));
    }
    s_avg[tid] = sum * (1.0f / (float)HWT);
    s_max[tid] = mx;
    __syncthreads();

    {   // hidden layer: 64 outputs (avg 0..31, max 32..63), 4 thr/output
        int oi = tid >> 2;
        int part = tid & 3;
        int j = oi & (HID - 1);
        const float* pool = (oi < HID) ? s_avg : s_max;
        float acc = 0.f;
        #pragma unroll 16
        for (int i = part * 64; i < part * 64 + 64; ++i)
            acc += pool[i] * w1[i * HID + j];
        acc += __shfl_down_sync(0xffffffffu, acc, 1);
        acc += __shfl_down_sync(0xffffffffu, acc, 2);
        if (part == 0) s_h[oi] = fmaxf(acc + b1[j], 0.f);
    }
    __syncthreads();

    {   // output layer: 2*b2 + (hA+hM) @ w2, sigmoid
        float acc = 2.0f * b2[tid];
        #pragma unroll
        for (int j = 0; j < HID; ++j)
            acc += (s_h[j] + s_h[HID + j]) * w2[j * CC + tid];
        g_scale[b][tid] = 1.0f / (1.0f + expf(-acc));
    }
}

// Kernel B: out = x * scale. grid (BLOCKS_S, GROUP), 256 thr. Reads mostly L2 hits.
__global__ void __launch_bounds__(256) scale_kernel(const float* __restrict__ x,
                                                    float* __restrict__ out,
                                                    int b0) {
    const int b   = b0 + blockIdx.y;
    const int tid = threadIdx.x;
    const float4 sc = reinterpret_cast<const float4*>(&g_scale[b][0])[tid & 63];

    const size_t base = (size_t)b * F4_PER_B + (size_t)blockIdx.x * F4_PER_SCTA;
    const float4* __restrict__ xi = reinterpret_cast<const float4*>(x) + base;
    float4* __restrict__ xo = reinterpret_cast<float4*>(out) + base;

    #pragma unroll 8
    for (int i = tid; i < F4_PER_SCTA; i += 256) {
        float4 v = __ldcs(xi + i);                 // last use: evict-first
        v.x *= sc.x; v.y *= sc.y; v.z *= sc.z; v.w *= sc.w;
        __stcs(xo + i, v);                         // streaming store
    }
}

extern "C" void kernel_launch(void* const* d_in, const int* in_sizes, int n_in,
                              void* d_out, int out_size) {
    const float* x  = (const float*)d_in[0];
    const float* w1 = (const float*)d_in[1];
    const float* b1 = (const float*)d_in[2];
    const float* w2 = (const float*)d_in[3];
    const float* b2 = (const float*)d_in[4];
    float* out = (float*)d_out;

    // Fork both worker streams off the capture (default) stream.
    cudaEventRecord(evRoot, 0);
    cudaStreamWaitEvent(s1, evRoot, 0);
    cudaStreamWaitEvent(s2, evRoot, 0);

    // Pipeline: pool(g) on s1, scale(g) on s2; scale(g) waits pool(g);
    // pool(g) waits scale(g-2) to bound the L2 window to 2 groups.
    for (int g = 0; g < NGRP; ++g) {
        if (g >= 2) cudaStreamWaitEvent(s1, evS[g - 2], 0);
        pool_mlp_kernel<<<dim3(KCTA, GROUP), 256, 0, s1>>>(x, w1, b1, w2, b2, g * GROUP);
        cudaEventRecord(evP[g], s1);
        cudaStreamWaitEvent(s2, evP[g], 0);
        scale_kernel<<<dim3(BLOCKS_S, GROUP), 256, 0, s2>>>(x, out, g * GROUP);
        cudaEventRecord(evS[g], s2);
    }

    // Join both streams back into the capture stream.
    cudaStreamWaitEvent(0, evP[NGRP - 1], 0);
    cudaStreamWaitEvent(0, evS[NGRP - 1], 0);
}

// round 7
// speedup vs baseline: 6.8564x; 1.0182x over previous
#include <cuda_runtime.h>
#include <math.h>

#define BB 32
#define HWT 12544              // 112*112
#define CC 256
#define HID 32
#define F4_PER_ROW 64          // 256 / 4

#define GROUP 8                // batches per group (103 MB <= 126 MB L2)
#define NGRP 4
#define KCTA 128               // CTAs per batch
#define ROWS_CTA 98            // HWT / KCTA
#define GRID_CTAS (KCTA * GROUP)   // 1024; 8/SM on 128 of 148 SMs -> all resident

__device__ float g_psum[GROUP][KCTA][CC];   // per-group scratch (reused)
__device__ float g_pmax[GROUP][KCTA][CC];
__device__ float g_scale[GROUP][CC];
__device__ int   g_arr[2 * NGRP];
__device__ int   g_rel[2 * NGRP];
__device__ int   g_ready[NGRP];

__global__ void init_kernel() {
    int t = threadIdx.x;
    if (t < 2 * NGRP) { g_arr[t] = 0; g_rel[t] = 0; }
    if (t < NGRP) g_ready[t] = 0;
}

__device__ __forceinline__ void grid_barrier(int slot) {
    __syncthreads();
    if (threadIdx.x == 0) {
        volatile int* rel = &g_rel[slot];
        __threadfence();                       // release my prior writes
        int old = atomicAdd(&g_arr[slot], 1);
        if (old == GRID_CTAS - 1) {
            *rel = 1;
        } else {
            while (*rel == 0) __nanosleep(64);
        }
        __threadfence();                       // acquire others' writes
    }
    __syncthreads();
}

__global__ void __launch_bounds__(256, 8) fused_bsp_kernel(
    const float* __restrict__ x,
    const float* __restrict__ w1, const float* __restrict__ b1,
    const float* __restrict__ w2, const float* __restrict__ b2,
    float* __restrict__ out)
{
    const int cta = blockIdx.x;
    const int bg  = cta >> 7;        // batch-in-group 0..7
    const int k   = cta & 127;       // slice 0..127
    const int tid = threadIdx.x;
    const int c4  = tid & 63;
    const int rg  = tid >> 6;

    __shared__ float4 s_sum[4][64];
    __shared__ float4 s_mx4[4][64];

    for (int g = 0; g < NGRP; ++g) {
        const int b = g * GROUP + bg;
        const size_t rowb = (size_t)b * HWT + (size_t)k * ROWS_CTA;
        const float4* __restrict__ xp =
            reinterpret_cast<const float4*>(x) + rowb * F4_PER_ROW + c4;

        // ---------- Phase A: pool group g (reads populate L2) ----------
        {
            float4 s = make_float4(0.f, 0.f, 0.f, 0.f);
            float4 m = make_float4(-INFINITY, -INFINITY, -INFINITY, -INFINITY);
            #pragma unroll 5
            for (int r = rg; r < ROWS_CTA; r += 4) {
                float4 v = __ldcg(xp + (size_t)r * F4_PER_ROW);
                s.x += v.x; s.y += v.y; s.z += v.z; s.w += v.w;
                m.x = fmaxf(m.x, v.x); m.y = fmaxf(m.y, v.y);
                m.z = fmaxf(m.z, v.z); m.w = fmaxf(m.w, v.w);
            }
            s_sum[rg][c4] = s;
            s_mx4[rg][c4] = m;
        }
        __syncthreads();
        if (rg == 0) {
            float4 a0 = s_sum[0][c4], a1 = s_sum[1][c4], a2 = s_sum[2][c4], a3 = s_sum[3][c4];
            float4 m0 = s_mx4[0][c4], m1 = s_mx4[1][c4], m2 = s_mx4[2][c4], m3 = s_mx4[3][c4];
            float4 ss = make_float4(a0.x + a1.x + a2.x + a3.x,
                                    a0.y + a1.y + a2.y + a3.y,
                                    a0.z + a1.z + a2.z + a3.z,
                                    a0.w + a1.w + a2.w + a3.w);
            float4 mm = make_float4(fmaxf(fmaxf(m0.x, m1.x), fmaxf(m2.x, m3.x)),
                                    fmaxf(fmaxf(m0.y, m1.y), fmaxf(m2.y, m3.y)),
                                    fmaxf(fmaxf(m0.z, m1.z), fmaxf(m2.z, m3.z)),
                                    fmaxf(fmaxf(m0.w, m1.w), fmaxf(m2.w, m3.w)));
            reinterpret_cast<float4*>(&g_psum[bg][k][0])[c4] = ss;
            reinterpret_cast<float4*>(&g_pmax[bg][k][0])[c4] = mm;
        }
        grid_barrier(2 * g);    // partials visible everywhere

        // ---------- Phase B: 8 CTAs run fan-in + MLP in parallel ----------
        if (cta < GROUP) {
            const int mb = cta;                 // batch-in-group this CTA handles
            __shared__ float s_avg[CC];
            __shared__ float s_max[CC];
            __shared__ float s_h[2 * HID];

            float sum = 0.f, mx = -INFINITY;
            #pragma unroll 16
            for (int q = 0; q < KCTA; ++q) {
                sum += __ldcg(&g_psum[mb][q][tid]);
                mx = fmaxf(mx, __ldcg(&g_pmax[mb][q][tid]));
            }
            s_avg[tid] = sum * (1.0f / (float)HWT);
            s_max[tid] = mx;
            __syncthreads();

            {   // hidden layer: 64 outputs, 4 threads each
                int oi = tid >> 2, part = tid & 3, j = oi & (HID - 1);
                const float* pool = (oi < HID) ? s_avg : s_max;
                float acc = 0.f;
                #pragma unroll 16
                for (int i = part * 64; i < part * 64 + 64; ++i)
                    acc += pool[i] * w1[i * HID + j];
                acc += __shfl_down_sync(0xffffffffu, acc, 1);
                acc += __shfl_down_sync(0xffffffffu, acc, 2);
                if (part == 0) s_h[oi] = fmaxf(acc + b1[j], 0.f);
            }
            __syncthreads();

            {   // output layer + sigmoid
                float acc = 2.0f * b2[tid];
                #pragma unroll
                for (int j = 0; j < HID; ++j)
                    acc += (s_h[j] + s_h[HID + j]) * w2[j * CC + tid];
                g_scale[mb][tid] = 1.0f / (1.0f + expf(-acc));
            }
            __threadfence();
            __syncthreads();
            if (tid == 0) atomicAdd(&g_ready[g], 1);
        }
        // everyone waits until all 8 scales for this group are published
        if (tid == 0) {
            while (((volatile int*)g_ready)[g] < GROUP) __nanosleep(64);
            __threadfence();
        }
        __syncthreads();

        // ---------- Phase C: scale group g (reads are L2-hot) ----------
        {
            const float4 sc =
                __ldcg(reinterpret_cast<const float4*>(&g_scale[bg][0]) + c4);
            float4* __restrict__ xo =
                reinterpret_cast<float4*>(out) + rowb * F4_PER_ROW + c4;
            #pragma unroll 5
            for (int r = rg; r < ROWS_CTA; r += 4) {
                float4 v = __ldcs(xp + (size_t)r * F4_PER_ROW);  // L2 hit, evict-first
                v.x *= sc.x; v.y *= sc.y; v.z *= sc.z; v.w *= sc.w;
                __stcs(xo + (size_t)r * F4_PER_ROW, v);
            }
        }
        grid_barrier(2 * g + 1);   // close L2 window before next group streams in
    }
}

extern "C" void kernel_launch(void* const* d_in, const int* in_sizes, int n_in,
                              void* d_out, int out_size) {
    const float* x  = (const float*)d_in[0];
    const float* w1 = (const float*)d_in[1];
    const float* b1 = (const float*)d_in[2];
    const float* w2 = (const float*)d_in[3];
    const float* b2 = (const float*)d_in[4];
    float* out = (float*)d_out;

    init_kernel<<<1, 32>>>();
    fused_bsp_kernel<<<GRID_CTAS, 256>>>(x, w1, b1, w2, b2, out);
}

// round 10
// speedup vs baseline: 9.3389x; 1.3621x over previous
#include <cuda_runtime.h>
#include <math.h>

#define BB 32
#define HWT 12544          // 112*112
#define CC 256
#define HID 32
#define CHUNKS 32          // pool CTAs per batch
#define ROWS_PER_CHUNK (HWT / CHUNKS)     // 392
#define RG 4
#define ROWS_PER_RG (ROWS_PER_CHUNK / RG) // 98
#define NPART (CHUNKS * RG)               // 128 partials per (b,c)
#define F4_PER_ROW (CC / 4)               // 64
#define F4_PER_B ((size_t)HWT * F4_PER_ROW)   // 802816
#define BLOCKS3 98
#define F4_PER_BLOCK3 (F4_PER_B / BLOCKS3)    // 8192

__device__ float g_psum[BB][NPART][CC];
__device__ float g_pmax[BB][NPART][CC];
__device__ float g_scale[BB][CC];
__device__ int   g_cnt[BB];               // zero at load; self-resetting

// Kernel 1: partial pooling + last-arrival fan-in MLP tail.
// grid (CHUNKS, BB), 256 threads. Thread = (rg, c4): one float4 channel
// group, 98 rows, LDG.128 fully coalesced (validated 6.48 TB/s).
__global__ void __launch_bounds__(256) pool_mlp_kernel(
    const float* __restrict__ x,
    const float* __restrict__ w1, const float* __restrict__ b1,
    const float* __restrict__ w2, const float* __restrict__ b2)
{
    const int b = blockIdx.y;
    const int chunk = blockIdx.x;
    const int tid = threadIdx.x;
    const int c4 = tid & 63;
    const int rg = tid >> 6;

    const size_t row0 = (size_t)b * HWT + (size_t)chunk * ROWS_PER_CHUNK + (size_t)rg * ROWS_PER_RG;
    const float4* __restrict__ xp = reinterpret_cast<const float4*>(x) + row0 * F4_PER_ROW + c4;

    float4 s = make_float4(0.f, 0.f, 0.f, 0.f);
    float4 m = make_float4(-INFINITY, -INFINITY, -INFINITY, -INFINITY);
    #pragma unroll 7
    for (int r = 0; r < ROWS_PER_RG; ++r) {
        float4 v = __ldcg(xp + (size_t)r * F4_PER_ROW);
        s.x += v.x; s.y += v.y; s.z += v.z; s.w += v.w;
        m.x = fmaxf(m.x, v.x); m.y = fmaxf(m.y, v.y);
        m.z = fmaxf(m.z, v.z); m.w = fmaxf(m.w, v.w);
    }
    const int p = chunk * RG + rg;
    reinterpret_cast<float4*>(&g_psum[b][p][0])[c4] = s;
    reinterpret_cast<float4*>(&g_pmax[b][p][0])[c4] = m;

    // ---- last-CTA-arrival fan-in: reduce 128 partials + MLP + sigmoid ----
    __shared__ int s_last;
    __threadfence();                       // release my partials
    __syncthreads();
    if (tid == 0) {
        int old = atomicAdd(&g_cnt[b], 1);
        s_last = (old == CHUNKS - 1);
        if (s_last) {
            g_cnt[b] = 0;                  // self-reset for graph replays
            __threadfence();               // acquire all partials
        }
    }
    __syncthreads();
    if (!s_last) return;

    __shared__ float s_avg[CC];
    __shared__ float s_max[CC];
    __shared__ float s_h[2 * HID];

    float sum = 0.f, mx = -INFINITY;
    #pragma unroll 16
    for (int q = 0; q < NPART; ++q) {
        sum += __ldcg(&g_psum[b][q][tid]);
        mx = fmaxf(mx, __ldcg(&g_pmax[b][q][tid]));
    }
    s_avg[tid] = sum * (1.0f / (float)HWT);
    s_max[tid] = mx;
    __syncthreads();

    {   // hidden layer: 64 outputs (avg 0..31, max 32..63), 4 threads/output
        int oi = tid >> 2;
        int part = tid & 3;
        int j = oi & (HID - 1);
        const float* pool = (oi < HID) ? s_avg : s_max;
        float acc = 0.f;
        #pragma unroll 16
        for (int i = part * 64; i < part * 64 + 64; ++i)
            acc += pool[i] * w1[i * HID + j];
        acc += __shfl_down_sync(0xffffffffu, acc, 1);
        acc += __shfl_down_sync(0xffffffffu, acc, 2);
        if (part == 0) s_h[oi] = fmaxf(acc + b1[j], 0.f);
    }
    __syncthreads();

    {   // output layer: 2*b2 + (hA+hM) @ w2, sigmoid
        float acc = 2.0f * b2[tid];
        #pragma unroll
        for (int j = 0; j < HID; ++j)
            acc += (s_h[j] + s_h[HID + j]) * w2[j * CC + tid];
        g_scale[b][tid] = 1.0f / (1.0f + expf(-acc));
    }
}

// Kernel 2: out = x * scale. grid (BLOCKS3, BB), 256 thr.
// DESCENDING batch order: first wave touches the batches the pool kernel
// read last (still resident in L2) -> ~120MB of reads become L2 hits.
__global__ void __launch_bounds__(256) scale_kernel(const float* __restrict__ x,
                                                    float* __restrict__ out) {
    const int b = (BB - 1) - blockIdx.y;   // descending
    const int tid = threadIdx.x;
    const float4 sc = reinterpret_cast<const float4*>(&g_scale[b][0])[tid & 63];

    const size_t base = (size_t)b * F4_PER_B + (size_t)blockIdx.x * F4_PER_BLOCK3;
    const float4* __restrict__ xi = reinterpret_cast<const float4*>(x) + base;
    float4* __restrict__ xo = reinterpret_cast<float4*>(out) + base;

    #pragma unroll 8
    for (int i = tid; i < F4_PER_BLOCK3; i += 256) {
        float4 v = __ldcs(xi + i);                 // last use: evict-first
        v.x *= sc.x; v.y *= sc.y; v.z *= sc.z; v.w *= sc.w;
        __stcs(xo + i, v);                         // streaming store
    }
}

extern "C" void kernel_launch(void* const* d_in, const int* in_sizes, int n_in,
                              void* d_out, int out_size) {
    const float* x  = (const float*)d_in[0];
    const float* w1 = (const float*)d_in[1];
    const float* b1 = (const float*)d_in[2];
    const float* w2 = (const float*)d_in[3];
    const float* b2 = (const float*)d_in[4];
    float* out = (float*)d_out;

    pool_mlp_kernel<<<dim3(CHUNKS, BB), 256>>>(x, w1, b1, w2, b2);
    scale_kernel<<<dim3(BLOCKS3, BB), 256>>>(x, out);
}